// round 15
// baseline (speedup 1.0000x reference)
#include <cuda_runtime.h>
#include <cuda_bf16.h>
#include <cuda_fp16.h>
#include <cstdint>

// Problem constants
#define B_  4
#define S_  2048
#define D_  1024
#define H_  16
#define HD_ 64
#define M_  (B_*S_)   // 8192

// ---------------- scratch (__device__ globals) ------------------------------
__device__ __half g_xq[(size_t)M_*D_], g_xk[(size_t)M_*D_], g_xv[(size_t)M_*D_];
__device__ __half g_wq[(size_t)D_*D_], g_wk[(size_t)D_*D_];
__device__ __half g_wv[(size_t)D_*D_], g_wo[(size_t)D_*D_];
__device__ __half g_q [(size_t)M_*D_];
__device__ __half g_k [(size_t)M_*D_];
__device__ __half g_v [(size_t)M_*D_];
__device__ __half g_kc[(size_t)M_*D_];
__device__ __half g_vt[(size_t)M_*D_];
__device__ __half g_hh[(size_t)M_*D_];
__device__ int g_cnt[B_];
__device__ int g_idx[B_][S_];

extern __shared__ char dynsmem[];

// 0.125 * log2(e)
#define SCALE_L2E 0.18033688011112042f

// ---------------- PTX helpers ------------------------------------------------
__device__ __forceinline__ uint32_t smem_u32(const void* p) {
    uint32_t a;
    asm("{ .reg .u64 t; cvta.to.shared.u64 t, %1; cvt.u32.u64 %0, t; }" : "=r"(a) : "l"(p));
    return a;
}
__device__ __forceinline__ void cp16(uint32_t dst, const void* src) {
    asm volatile("cp.async.cg.shared.global [%0], [%1], 16;" :: "r"(dst), "l"(src) : "memory");
}
__device__ __forceinline__ void cp_commit() {
    asm volatile("cp.async.commit_group;" ::: "memory");
}
__device__ __forceinline__ void ldsm4(uint32_t* r, uint32_t addr) {
    asm volatile("ldmatrix.sync.aligned.m8n8.x4.shared.b16 {%0,%1,%2,%3}, [%4];"
                 : "=r"(r[0]), "=r"(r[1]), "=r"(r[2]), "=r"(r[3]) : "r"(addr));
}
__device__ __forceinline__ void mma_f16(float* d, const uint32_t* a, const uint32_t* b) {
    asm volatile(
        "mma.sync.aligned.m16n8k16.row.col.f32.f16.f16.f32 "
        "{%0,%1,%2,%3}, {%4,%5,%6,%7}, {%8,%9}, {%0,%1,%2,%3};"
        : "+f"(d[0]), "+f"(d[1]), "+f"(d[2]), "+f"(d[3])
        : "r"(a[0]), "r"(a[1]), "r"(a[2]), "r"(a[3]), "r"(b[0]), "r"(b[1]));
}
__device__ __forceinline__ uint32_t pack2h(float x0, float x1) {
    __half2 h = __floats2half2_rn(x0, x1);
    return *(uint32_t*)&h;
}

// ---------------- fused conversion kernel ------------------------------------
__global__ __launch_bounds__(256) void cvt_all_kernel(
    const float* __restrict__ xq, const float* __restrict__ xk, const float* __restrict__ xv,
    const float* __restrict__ Wq, const float* __restrict__ Wk,
    const float* __restrict__ Wv, const float* __restrict__ Wo,
    __half* __restrict__ oxq, __half* __restrict__ oxk, __half* __restrict__ oxv,
    __half* __restrict__ owq, __half* __restrict__ owk,
    __half* __restrict__ owv, __half* __restrict__ owo)
{
    const int y = blockIdx.y;
    int i = blockIdx.x * blockDim.x + threadIdx.x;
    const int n4 = (y < 3) ? (M_ * D_ / 4) : (D_ * D_ / 4);
    if (i >= n4) return;
    const float* s = y == 0 ? xq : (y == 1 ? xk : (y == 2 ? xv :
                     (y == 3 ? Wq : (y == 4 ? Wk : (y == 5 ? Wv : Wo)))));
    __half* o = y == 0 ? oxq : (y == 1 ? oxk : (y == 2 ? oxv :
                (y == 3 ? owq : (y == 4 ? owk : (y == 5 ? owv : owo)))));
    float4 v = ((const float4*)s)[i];
    ((uint2*)o)[i] = make_uint2(pack2h(v.x, v.y), pack2h(v.z, v.w));
}

// ---------------- mask compaction: one block per batch -----------------------
__global__ __launch_bounds__(256) void mask_compact_kernel(const int* __restrict__ mask)
{
    __shared__ int warp_off[8];
    const int b = blockIdx.x;
    const int tid = threadIdx.x, lane = tid & 31, wid = tid >> 5;
    const int* m = mask + b * S_;
    int vals[8], c = 0;
#pragma unroll
    for (int i = 0; i < 8; i++) { vals[i] = m[tid * 8 + i]; c += (vals[i] != 0); }
    int pre = c;
#pragma unroll
    for (int off = 1; off < 32; off <<= 1) {
        int t = __shfl_up_sync(0xffffffffu, pre, off);
        if (lane >= off) pre += t;
    }
    if (lane == 31) warp_off[wid] = pre;
    __syncthreads();
    if (tid == 0) {
        int s = 0;
#pragma unroll
        for (int i = 0; i < 8; i++) { int t = warp_off[i]; warp_off[i] = s; s += t; }
        g_cnt[b] = s;
    }
    __syncthreads();
    int pos = warp_off[wid] + pre - c;
#pragma unroll
    for (int i = 0; i < 8; i++)
        if (vals[i]) g_idx[b][pos++] = tid * 8 + i;
}

// ---------------- fp16 1-call GEMM, BK=64, 3-stage pipeline ------------------
#define BM 128
#define BN 128
#define GBK 64
#define ROWB 144
#define TILEB (128 * ROWB)      // 18432
#define BUFB  (2 * TILEB)       // 36864 (A + B)
#define GEMM_SMEM (3 * BUFB)    // 110592

__device__ __forceinline__ void g2s_chunk(
    uint32_t sbuf, const __half* Ap, const __half* Bw, int tid)
{
    int row = tid >> 1, h64 = tid & 1;
    uint32_t soff = (uint32_t)row * ROWB + (uint32_t)h64 * 64;
    size_t goff = (size_t)row * D_ + h64 * 32;
#pragma unroll
    for (int j = 0; j < 4; j++) {
        cp16(sbuf + soff + j * 16, Ap + goff + j * 8);
        cp16(sbuf + TILEB + soff + j * 16, Bw + goff + j * 8);
    }
}

__device__ __forceinline__ void gemm_mainloop(
    uint32_t sb, const __half* Ap, const __half* Bp,
    int tid, int lane, int wm, int wn, float acc[4][4][4])
{
#pragma unroll
    for (int i = 0; i < 4; i++)
#pragma unroll
        for (int j = 0; j < 4; j++)
#pragma unroll
            for (int k = 0; k < 4; k++) acc[i][j][k] = 0.f;

    g2s_chunk(sb,        Ap,       Bp,       tid); cp_commit();
    g2s_chunk(sb + BUFB, Ap + GBK, Bp + GBK, tid); cp_commit();

    const int lr = lane & 7, lq = lane >> 3;
    const uint32_t a_base_off =
        (uint32_t)(wm * 64 + (lq & 1) * 8 + lr) * ROWB + (uint32_t)((lq >> 1) * 8) * 2;
    const uint32_t b_base_off =
        (uint32_t)(wn * 32 + (lq >> 1) * 8 + lr) * ROWB + (uint32_t)((lq & 1) * 8) * 2;

    const int NCHUNK = D_ / GBK;   // 16
    int cur = 0, nxt = 2;
#pragma unroll 1
    for (int c = 0; c < NCHUNK; c++) {
        if (c >= NCHUNK - 2) asm volatile("cp.async.wait_group 0;" ::: "memory");
        else                 asm volatile("cp.async.wait_group 1;" ::: "memory");
        __syncthreads();

        const uint32_t buf = sb + (uint32_t)cur * BUFB;
        const uint32_t sA = buf, sB = buf + TILEB;

#pragma unroll
        for (int ks = 0; ks < 4; ks++) {
            const uint32_t ko = (uint32_t)ks * 32;
            uint32_t ar[4][4], br[2][4];
#pragma unroll
            for (int mt = 0; mt < 4; mt++)
                ldsm4(ar[mt], sA + a_base_off + ko + (uint32_t)mt * (16 * ROWB));
#pragma unroll
            for (int np = 0; np < 2; np++)
                ldsm4(br[np], sB + b_base_off + ko + (uint32_t)np * (16 * ROWB));
#pragma unroll
            for (int mt = 0; mt < 4; mt++)
#pragma unroll
                for (int nt = 0; nt < 4; nt++)
                    mma_f16(acc[mt][nt], ar[mt], &br[nt >> 1][(nt & 1) * 2]);
        }

        if (c + 2 < NCHUNK) {
            const int kc = (c + 2) * GBK;
            g2s_chunk(sb + (uint32_t)nxt * BUFB, Ap + kc, Bp + kc, tid);
            cp_commit();
        }
        cur = cur == 2 ? 0 : cur + 1;
        nxt = nxt == 2 ? 0 : nxt + 1;
    }
}

// Fused projection GEMM: grid.z selects (X, W, bias, out, scale).
__global__ __launch_bounds__(256) void gemm_proj_kernel(
    const __half* __restrict__ xq, const __half* __restrict__ xk,
    const __half* __restrict__ xv,
    const __half* __restrict__ wq, const __half* __restrict__ wk,
    const __half* __restrict__ wv,
    const float* __restrict__ bq, const float* __restrict__ bk,
    const float* __restrict__ bv,
    __half* __restrict__ oq, __half* __restrict__ ok, __half* __restrict__ ov)
{
    const uint32_t sb = smem_u32(dynsmem);
    const int tid = threadIdx.x, wid = tid >> 5, lane = tid & 31;
    const int wm = wid >> 2, wn = wid & 3;
    const int n0 = blockIdx.x * BN, m0 = blockIdx.y * BM;
    const int z = blockIdx.z;

    const __half* Ab  = z == 0 ? xq : (z == 1 ? xk : xv);
    const __half* Wb  = z == 0 ? wq : (z == 1 ? wk : wv);
    const float* bias = z == 0 ? bq : (z == 1 ? bk : bv);
    __half* outp      = z == 0 ? oq : (z == 1 ? ok : ov);
    const float oscale = z == 0 ? SCALE_L2E : 1.0f;

    float acc[4][4][4];
    gemm_mainloop(sb, Ab + (size_t)m0 * D_, Wb + (size_t)n0 * D_,
                  tid, lane, wm, wn, acc);

    const int g = lane >> 2, tq = lane & 3;
#pragma unroll
    for (int mt = 0; mt < 4; mt++) {
#pragma unroll
        for (int nt = 0; nt < 4; nt++) {
            int row = m0 + wm * 64 + mt * 16 + g;
            int col = n0 + wn * 32 + nt * 8 + tq * 2;
            float2 bv2 = *(const float2*)&bias[col];
            float v0 = (acc[mt][nt][0] + bv2.x) * oscale;
            float v1 = (acc[mt][nt][1] + bv2.y) * oscale;
            float v2 = (acc[mt][nt][2] + bv2.x) * oscale;
            float v3 = (acc[mt][nt][3] + bv2.y) * oscale;
            int bb = row >> 11, s = row & 2047, hh = col >> 6, d = col & 63;
            size_t i0 = ((size_t)(bb * H_ + hh) * S_ + s) * HD_ + d;
            size_t i1 = i0 + 8 * HD_;
            *(uint32_t*)&outp[i0] = pack2h(v0, v1);
            *(uint32_t*)&outp[i1] = pack2h(v2, v3);
        }
    }
}

// Final GEMM: single-A fp16, fp32 out.
__global__ __launch_bounds__(256) void gemm_out_kernel(
    const __half* __restrict__ Ahi, const __half* __restrict__ Bw,
    const float* __restrict__ bias, float* __restrict__ out)
{
    const uint32_t sb = smem_u32(dynsmem);
    const int tid = threadIdx.x, wid = tid >> 5, lane = tid & 31;
    const int wm = wid >> 2, wn = wid & 3;
    const int n0 = blockIdx.x * BN, m0 = blockIdx.y * BM;

    float acc[4][4][4];
    gemm_mainloop(sb, Ahi + (size_t)m0 * D_, Bw + (size_t)n0 * D_,
                  tid, lane, wm, wn, acc);

    const int g = lane >> 2, tq = lane & 3;
#pragma unroll
    for (int mt = 0; mt < 4; mt++) {
#pragma unroll
        for (int nt = 0; nt < 4; nt++) {
            int row = m0 + wm * 64 + mt * 16 + g;
            int col = n0 + wn * 32 + nt * 8 + tq * 2;
            float2 bv2 = *(const float2*)&bias[col];
            *(float2*)&out[(size_t)row * D_ + col] =
                make_float2(acc[mt][nt][0] + bv2.x, acc[mt][nt][1] + bv2.y);
            *(float2*)&out[(size_t)(row + 8) * D_ + col] =
                make_float2(acc[mt][nt][2] + bv2.x, acc[mt][nt][3] + bv2.y);
        }
    }
}

// ---------------- gather: compact K rows; compact + transpose V --------------
__global__ __launch_bounds__(256) void gather_kv_kernel()
{
    __shared__ __align__(16) unsigned short ts[64 * 66];
    __shared__ int sidx[64];
    const int b = blockIdx.z, h = blockIdx.y, st = blockIdx.x;
    const int bh = b * H_ + h;
    const int j0 = st * 64;
    const int tid = threadIdx.x;
    const int cnt = g_cnt[b];

    if (tid < 64) sidx[tid] = (j0 + tid < cnt) ? g_idx[b][j0 + tid] : -1;
    __syncthreads();

    {
        int r = tid >> 2, part = tid & 3;
        int s = sidx[r];
        const uint4* srcp = (const uint4*)(g_k + ((size_t)bh * S_ + (s < 0 ? 0 : s)) * HD_)
                            + part * 2;
        uint4 z = make_uint4(0, 0, 0, 0);
        uint4 v0 = s >= 0 ? srcp[0] : z;
        uint4 v1 = s >= 0 ? srcp[1] : z;
        uint4* dstp = (uint4*)(g_kc + ((size_t)bh * S_ + j0 + r) * HD_) + part * 2;
        dstp[0] = v0;
        dstp[1] = v1;
    }

#pragma unroll
    for (int i = 0; i < 8; i++) {
        int flat = tid + i * 256;
        int r = flat >> 5, c2 = flat & 31;
        int s = sidx[r];
        uint32_t v = 0;
        if (s >= 0)
            v = ((const uint32_t*)(g_v + ((size_t)bh * S_ + s) * HD_))[c2];
        *(uint32_t*)&ts[r * 66 + c2 * 2] = v;
    }
    __syncthreads();
    uint32_t* dst = (uint32_t*)(g_vt + (size_t)bh * HD_ * S_ + j0);
#pragma unroll
    for (int i = 0; i < 8; i++) {
        int flat = tid + i * 256;
        int d = flat >> 5, sp = flat & 31;
        uint32_t v = (uint32_t)ts[(2 * sp) * 66 + d] |
                     ((uint32_t)ts[(2 * sp + 1) * 66 + d] << 16);
        dst[(size_t)d * (S_ / 2) + sp] = v;
    }
}

// ---------------- tensor-core flash attention, 3-stage, h2exp2 softmax -------
#define FQ   0u
#define FKV  18432u
#define FBUF 18432u
#define FLASH_SMEM 73728   // Q + 3 KV stages

__global__ __launch_bounds__(256) void flash_tc_kernel()
{
    char* sm = dynsmem;
    const uint32_t sb = smem_u32(sm);
    const int tid = threadIdx.x, w = tid >> 5, lane = tid & 31;
    const int lr = lane & 7, lq = lane >> 3, g = lane >> 2, q = lane & 3;
    const int b = blockIdx.z, h = blockIdx.y;
    const int bh = b * H_ + h;
    const int q0 = blockIdx.x * 128;

    const int cnt = g_cnt[b];
    int nkt = (cnt + 63) >> 6;
    if (nkt < 1) nkt = 1;

    const __half* Qp  = g_q  + ((size_t)bh * S_ + q0) * HD_;
    const __half* Kp  = g_kc + (size_t)bh * S_ * HD_;
    const __half* Vtp = g_vt + (size_t)bh * HD_ * S_;

    {
        int r = tid >> 1, halfr = tid & 1;
        const __half* src = Qp + (size_t)r * HD_ + halfr * 32;
        uint32_t dst = sb + FQ + (uint32_t)r * 144u + (uint32_t)halfr * 64u;
#pragma unroll
        for (int j = 0; j < 4; j++) cp16(dst + j * 16, src + j * 8);
    }
    cp_commit();

    auto load_tile = [&](int kt, int buf) {
        int k0 = kt * 64;
        int which = tid & 1;
        int halfr = (tid >> 1) & 1;
        int r = tid >> 2;
        uint32_t dst = sb + FKV + (uint32_t)buf * FBUF + (uint32_t)which * 9216u +
                       (uint32_t)r * 144u + (uint32_t)halfr * 64u;
        const __half* src = which ? (Vtp + (size_t)r * S_ + k0 + halfr * 32)
                                  : (Kp + (size_t)(k0 + r) * HD_ + halfr * 32);
#pragma unroll
        for (int j = 0; j < 4; j++) cp16(dst + j * 16, src + j * 8);
        cp_commit();
    };
    load_tile(0, 0);
    load_tile(1, 1);

    asm volatile("cp.async.wait_group 2;" ::: "memory");
    __syncthreads();

    uint32_t qf[4][4];
    {
        uint32_t aoff = (uint32_t)(w * 16 + (lq & 1) * 8 + lr) * 144u +
                        (uint32_t)((lq >> 1) * 8) * 2u;
#pragma unroll
        for (int ks = 0; ks < 4; ks++)
            ldsm4(qf[ks], sb + FQ + aoff + ks * 32);
    }

    float o[8][4];
#pragma unroll
    for (int i = 0; i < 8; i++) { o[i][0] = o[i][1] = o[i][2] = o[i][3] = 0.f; }
    float m0r = -1e30f, m1r = -1e30f, l0 = 0.f, l1 = 0.f;
    const uint32_t boff = (uint32_t)((lq >> 1) * 8 + lr) * 144u +
                          (uint32_t)((lq & 1) * 8) * 2u;

    int cur = 0, nxt = 2;
#pragma unroll 1
    for (int kt = 0; kt < nkt; kt++) {
        if (kt >= nkt - 2) asm volatile("cp.async.wait_group 0;" ::: "memory");
        else               asm volatile("cp.async.wait_group 1;" ::: "memory");
        __syncthreads();

        const uint32_t kb = sb + FKV + (uint32_t)cur * FBUF;

        float sc[8][4];
#pragma unroll
        for (int i = 0; i < 8; i++) { sc[i][0] = sc[i][1] = sc[i][2] = sc[i][3] = 0.f; }

#pragma unroll
        for (int ks = 0; ks < 4; ks++) {
            uint32_t kf[4][4];
#pragma unroll
            for (int np = 0; np < 4; np++)
                ldsm4(kf[np], kb + boff + (uint32_t)np * 2304u + ks * 32);
#pragma unroll
            for (int nt = 0; nt < 8; nt++)
                mma_f16(sc[nt], qf[ks], &kf[nt >> 1][(nt & 1) * 2]);
        }

        if (kt + 2 < nkt) load_tile(kt + 2, nxt);

#pragma unroll
        for (int nt = 0; nt < 8; nt++) {
            int j = kt * 64 + nt * 8 + q * 2;
            bool p0 = j < cnt, p1 = j + 1 < cnt;
            sc[nt][0] = p0 ? sc[nt][0] : -1e10f;
            sc[nt][1] = p1 ? sc[nt][1] : -1e10f;
            sc[nt][2] = p0 ? sc[nt][2] : -1e10f;
            sc[nt][3] = p1 ? sc[nt][3] : -1e10f;
        }

        float tm0 = -1e30f, tm1 = -1e30f;
#pragma unroll
        for (int nt = 0; nt < 8; nt++) {
            tm0 = fmaxf(tm0, fmaxf(sc[nt][0], sc[nt][1]));
            tm1 = fmaxf(tm1, fmaxf(sc[nt][2], sc[nt][3]));
        }
        tm0 = fmaxf(tm0, __shfl_xor_sync(0xffffffffu, tm0, 1));
        tm0 = fmaxf(tm0, __shfl_xor_sync(0xffffffffu, tm0, 2));
        tm1 = fmaxf(tm1, __shfl_xor_sync(0xffffffffu, tm1, 1));
        tm1 = fmaxf(tm1, __shfl_xor_sync(0xffffffffu, tm1, 2));
        float nm0 = fmaxf(m0r, tm0), nm1 = fmaxf(m1r, tm1);
        float al0 = exp2f(m0r - nm0), al1 = exp2f(m1r - nm1);
        m0r = nm0; m1r = nm1;

        // p = exp2(s - m) computed in fp16x2 (one MUFU per pair);
        // fragments fall out directly, sums accumulated in fp32.
        uint32_t pe[8][2];
        float rs0 = 0.f, rs1 = 0.f;
#pragma unroll
        for (int nt = 0; nt < 8; nt++) {
            __half2 h01 = h2exp2(__floats2half2_rn(sc[nt][0] - nm0, sc[nt][1] - nm0));
            __half2 h23 = h2exp2(__floats2half2_rn(sc[nt][2] - nm1, sc[nt][3] - nm1));
            pe[nt][0] = *(uint32_t*)&h01;
            pe[nt][1] = *(uint32_t*)&h23;
            float2 f01 = __half22float2(h01);
            float2 f23 = __half22float2(h23);
            rs0 += f01.x + f01.y;
            rs1 += f23.x + f23.y;
        }
        rs0 += __shfl_xor_sync(0xffffffffu, rs0, 1);
        rs0 += __shfl_xor_sync(0xffffffffu, rs0, 2);
        rs1 += __shfl_xor_sync(0xffffffffu, rs1, 1);
        rs1 += __shfl_xor_sync(0xffffffffu, rs1, 2);
        l0 = l0 * al0 + rs0;
        l1 = l1 * al1 + rs1;
#pragma unroll
        for (int nt = 0; nt < 8; nt++) {
            o[nt][0] *= al0; o[nt][1] *= al0; o[nt][2] *= al1; o[nt][3] *= al1;
        }

#pragma unroll
        for (int ks = 0; ks < 4; ks++) {
            const int t0 = 2 * ks, t1 = t0 + 1;
            uint32_t ah[4];
            ah[0] = pe[t0][0];
            ah[1] = pe[t0][1];
            ah[2] = pe[t1][0];
            ah[3] = pe[t1][1];
            uint32_t vf[4][4];
#pragma unroll
            for (int np = 0; np < 4; np++)
                ldsm4(vf[np], kb + 9216u + boff + (uint32_t)np * 2304u + ks * 32);
#pragma unroll
            for (int nt = 0; nt < 8; nt++)
                mma_f16(o[nt], ah, &vf[nt >> 1][(nt & 1) * 2]);
        }
        cur = cur == 2 ? 0 : cur + 1;
        nxt = nxt == 2 ? 0 : nxt + 1;
    }

    float inv0 = 1.f / l0, inv1 = 1.f / l1;
    size_t row0 = (size_t)(b * S_ + q0 + w * 16 + g);
    int colb = h * HD_;
#pragma unroll
    for (int nt = 0; nt < 8; nt++) {
        int col = colb + nt * 8 + q * 2;
        *(uint32_t*)&g_hh[row0 * D_ + col] = pack2h(o[nt][0] * inv0, o[nt][1] * inv0);
        *(uint32_t*)&g_hh[(row0 + 8) * D_ + col] = pack2h(o[nt][2] * inv1, o[nt][3] * inv1);
    }
}

// ---------------------------------------------------------------------------
extern "C" void kernel_launch(void* const* d_in, const int* in_sizes, int n_in,
                              void* d_out, int out_size)
{
    const float* query = (const float*)d_in[0];
    const float* key   = (const float*)d_in[1];
    const float* value = (const float*)d_in[2];
    const int*   mask  = (const int*)d_in[3];
    const float* Wq = (const float*)d_in[4];
    const float* bq = (const float*)d_in[5];
    const float* Wk = (const float*)d_in[6];
    const float* bk = (const float*)d_in[7];
    const float* Wv = (const float*)d_in[8];
    const float* bv = (const float*)d_in[9];
    const float* Wo = (const float*)d_in[10];
    const float* bo = (const float*)d_in[11];
    float* out = (float*)d_out;

    __half *xq,*xk,*xv,*wq,*wk,*wv,*wo,*hh,*qq,*kk,*vv;
    cudaGetSymbolAddress((void**)&xq, g_xq);
    cudaGetSymbolAddress((void**)&xk, g_xk);
    cudaGetSymbolAddress((void**)&xv, g_xv);
    cudaGetSymbolAddress((void**)&wq, g_wq);
    cudaGetSymbolAddress((void**)&wk, g_wk);
    cudaGetSymbolAddress((void**)&wv, g_wv);
    cudaGetSymbolAddress((void**)&wo, g_wo);
    cudaGetSymbolAddress((void**)&qq, g_q);
    cudaGetSymbolAddress((void**)&kk, g_k);
    cudaGetSymbolAddress((void**)&vv, g_v);
    cudaGetSymbolAddress((void**)&hh, g_hh);

    static int attr_set = 0;
    if (!attr_set) {
        cudaFuncSetAttribute((const void*)gemm_proj_kernel,
                             cudaFuncAttributeMaxDynamicSharedMemorySize, GEMM_SMEM);
        cudaFuncSetAttribute((const void*)gemm_out_kernel,
                             cudaFuncAttributeMaxDynamicSharedMemorySize, GEMM_SMEM);
        cudaFuncSetAttribute((const void*)flash_tc_kernel,
                             cudaFuncAttributeMaxDynamicSharedMemorySize, FLASH_SMEM);
        attr_set = 1;
    }

    const int NX4 = M_ * D_ / 4;
    cvt_all_kernel<<<dim3((NX4 + 255) / 256, 7), 256>>>(
        query, key, value, Wq, Wk, Wv, Wo, xq, xk, xv, wq, wk, wv, wo);

    mask_compact_kernel<<<B_, 256>>>(mask);

    gemm_proj_kernel<<<dim3(D_ / BN, M_ / BM, 3), 256, GEMM_SMEM>>>(
        xq, xk, xv, wq, wk, wv, bq, bk, bv, qq, kk, vv);

    gather_kv_kernel<<<dim3(S_ / 64, H_, B_), 256>>>();

    flash_tc_kernel<<<dim3(S_ / 128, H_, B_), 256, FLASH_SMEM>>>();

    gemm_out_kernel<<<dim3(D_ / BN, M_ / BM), 256, GEMM_SMEM>>>(hh, wo, bo, out);
}

// round 16
// speedup vs baseline: 1.1489x; 1.1489x over previous
#include <cuda_runtime.h>
#include <cuda_bf16.h>
#include <cuda_fp16.h>
#include <cstdint>

// Problem constants
#define B_  4
#define S_  2048
#define D_  1024
#define H_  16
#define HD_ 64
#define M_  (B_*S_)   // 8192

// ---------------- scratch (__device__ globals) ------------------------------
__device__ __half g_xq[(size_t)M_*D_], g_xk[(size_t)M_*D_], g_xv[(size_t)M_*D_];
__device__ __half g_wq[(size_t)D_*D_], g_wk[(size_t)D_*D_];
__device__ __half g_wv[(size_t)D_*D_], g_wo[(size_t)D_*D_];
__device__ __half g_q [(size_t)M_*D_];
__device__ __half g_k [(size_t)M_*D_];
__device__ __half g_v [(size_t)M_*D_];
__device__ __half g_kc[(size_t)M_*D_];
__device__ __half g_vt[(size_t)M_*D_];
__device__ __half g_hh[(size_t)M_*D_];
__device__ int g_cnt[B_];
__device__ int g_idx[B_][S_];

extern __shared__ char dynsmem[];

// 0.125 * log2(e)
#define SCALE_L2E 0.18033688011112042f

// ---------------- PTX helpers ------------------------------------------------
__device__ __forceinline__ uint32_t smem_u32(const void* p) {
    uint32_t a;
    asm("{ .reg .u64 t; cvta.to.shared.u64 t, %1; cvt.u32.u64 %0, t; }" : "=r"(a) : "l"(p));
    return a;
}
__device__ __forceinline__ void cp16(uint32_t dst, const void* src) {
    asm volatile("cp.async.cg.shared.global [%0], [%1], 16;" :: "r"(dst), "l"(src) : "memory");
}
__device__ __forceinline__ void cp_commit() {
    asm volatile("cp.async.commit_group;" ::: "memory");
}
__device__ __forceinline__ void ldsm4(uint32_t* r, uint32_t addr) {
    asm volatile("ldmatrix.sync.aligned.m8n8.x4.shared.b16 {%0,%1,%2,%3}, [%4];"
                 : "=r"(r[0]), "=r"(r[1]), "=r"(r[2]), "=r"(r[3]) : "r"(addr));
}
__device__ __forceinline__ void mma_f16(float* d, const uint32_t* a, const uint32_t* b) {
    asm volatile(
        "mma.sync.aligned.m16n8k16.row.col.f32.f16.f16.f32 "
        "{%0,%1,%2,%3}, {%4,%5,%6,%7}, {%8,%9}, {%0,%1,%2,%3};"
        : "+f"(d[0]), "+f"(d[1]), "+f"(d[2]), "+f"(d[3])
        : "r"(a[0]), "r"(a[1]), "r"(a[2]), "r"(a[3]), "r"(b[0]), "r"(b[1]));
}
__device__ __forceinline__ uint32_t pack2h(float x0, float x1) {
    __half2 h = __floats2half2_rn(x0, x1);
    return *(uint32_t*)&h;
}

// ---------------- fused conversion kernel ------------------------------------
__global__ __launch_bounds__(256) void cvt_all_kernel(
    const float* __restrict__ xq, const float* __restrict__ xk, const float* __restrict__ xv,
    const float* __restrict__ Wq, const float* __restrict__ Wk,
    const float* __restrict__ Wv, const float* __restrict__ Wo,
    __half* __restrict__ oxq, __half* __restrict__ oxk, __half* __restrict__ oxv,
    __half* __restrict__ owq, __half* __restrict__ owk,
    __half* __restrict__ owv, __half* __restrict__ owo)
{
    const int y = blockIdx.y;
    int i = blockIdx.x * blockDim.x + threadIdx.x;
    const int n4 = (y < 3) ? (M_ * D_ / 4) : (D_ * D_ / 4);
    if (i >= n4) return;
    const float* s = y == 0 ? xq : (y == 1 ? xk : (y == 2 ? xv :
                     (y == 3 ? Wq : (y == 4 ? Wk : (y == 5 ? Wv : Wo)))));
    __half* o = y == 0 ? oxq : (y == 1 ? oxk : (y == 2 ? oxv :
                (y == 3 ? owq : (y == 4 ? owk : (y == 5 ? owv : owo)))));
    float4 v = ((const float4*)s)[i];
    ((uint2*)o)[i] = make_uint2(pack2h(v.x, v.y), pack2h(v.z, v.w));
}

// ---------------- mask compaction: one block per batch -----------------------
__global__ __launch_bounds__(256) void mask_compact_kernel(const int* __restrict__ mask)
{
    __shared__ int warp_off[8];
    const int b = blockIdx.x;
    const int tid = threadIdx.x, lane = tid & 31, wid = tid >> 5;
    const int* m = mask + b * S_;
    int vals[8], c = 0;
#pragma unroll
    for (int i = 0; i < 8; i++) { vals[i] = m[tid * 8 + i]; c += (vals[i] != 0); }
    int pre = c;
#pragma unroll
    for (int off = 1; off < 32; off <<= 1) {
        int t = __shfl_up_sync(0xffffffffu, pre, off);
        if (lane >= off) pre += t;
    }
    if (lane == 31) warp_off[wid] = pre;
    __syncthreads();
    if (tid == 0) {
        int s = 0;
#pragma unroll
        for (int i = 0; i < 8; i++) { int t = warp_off[i]; warp_off[i] = s; s += t; }
        g_cnt[b] = s;
    }
    __syncthreads();
    int pos = warp_off[wid] + pre - c;
#pragma unroll
    for (int i = 0; i < 8; i++)
        if (vals[i]) g_idx[b][pos++] = tid * 8 + i;
}

// ---------------- fp16 1-call GEMM, BK=32, 4-stage pipeline ------------------
#define BM 128
#define BN 128
#define GBK 32
#define ROWB 80
#define TILEB (128 * ROWB)
#define BUFB  (2 * TILEB)       // A, B = 20480
#define GEMM_SMEM (4 * BUFB)    // 81920

__device__ __forceinline__ void g2s_chunk(
    uint32_t sbuf, const __half* Ap, const __half* Bw, int tid)
{
#pragma unroll
    for (int r = 0; r < 2; r++) {
        int c = tid + (r << 8);
        int row = c >> 2, c16 = c & 3;
        uint32_t soff = (uint32_t)row * ROWB + (uint32_t)c16 * 16;
        size_t goff = (size_t)row * D_ + c16 * 8;
        cp16(sbuf + 0 * TILEB + soff, Ap + goff);
        cp16(sbuf + 1 * TILEB + soff, Bw + goff);
    }
}

__device__ __forceinline__ void gemm_mainloop(
    uint32_t sb, const __half* Ap, const __half* Bp,
    int tid, int lane, int wm, int wn, float acc[4][4][4])
{
#pragma unroll
    for (int i = 0; i < 4; i++)
#pragma unroll
        for (int j = 0; j < 4; j++)
#pragma unroll
            for (int k = 0; k < 4; k++) acc[i][j][k] = 0.f;

    // prologue: 3 chunks in flight
    g2s_chunk(sb,            Ap,           Bp,           tid); cp_commit();
    g2s_chunk(sb + BUFB,     Ap + GBK,     Bp + GBK,     tid); cp_commit();
    g2s_chunk(sb + 2 * BUFB, Ap + 2 * GBK, Bp + 2 * GBK, tid); cp_commit();

    const int lr = lane & 7, lq = lane >> 3;
    const uint32_t a_base_off =
        (uint32_t)(wm * 64 + (lq & 1) * 8 + lr) * ROWB + (uint32_t)((lq >> 1) * 8) * 2;
    const uint32_t b_base_off =
        (uint32_t)(wn * 32 + (lq >> 1) * 8 + lr) * ROWB + (uint32_t)((lq & 1) * 8) * 2;

    const int NCHUNK = D_ / GBK;   // 32
    int cur = 0, nxt = 3;          // buffer indices mod 4, prefetch distance 3
#pragma unroll 1
    for (int c = 0; c < NCHUNK; c++) {
        if (c >= NCHUNK - 3) asm volatile("cp.async.wait_group 0;" ::: "memory");
        else                 asm volatile("cp.async.wait_group 2;" ::: "memory");
        __syncthreads();

        const uint32_t buf = sb + (uint32_t)cur * BUFB;
        const uint32_t sA = buf, sB = buf + TILEB;

#pragma unroll
        for (int ks = 0; ks < 2; ks++) {
            const uint32_t ko = (uint32_t)(ks * 16) * 2;
            uint32_t ar[4][4], br[2][4];
#pragma unroll
            for (int mt = 0; mt < 4; mt++)
                ldsm4(ar[mt], sA + a_base_off + ko + (uint32_t)mt * (16 * ROWB));
#pragma unroll
            for (int np = 0; np < 2; np++)
                ldsm4(br[np], sB + b_base_off + ko + (uint32_t)np * (16 * ROWB));
#pragma unroll
            for (int mt = 0; mt < 4; mt++)
#pragma unroll
                for (int nt = 0; nt < 4; nt++)
                    mma_f16(acc[mt][nt], ar[mt], &br[nt >> 1][(nt & 1) * 2]);
        }

        // prefetch chunk c+3 into buffer last read at iteration c-1
        if (c + 3 < NCHUNK) {
            const int kc = (c + 3) * GBK;
            g2s_chunk(sb + (uint32_t)nxt * BUFB, Ap + kc, Bp + kc, tid);
            cp_commit();
        }
        cur = (cur + 1) & 3;
        nxt = (nxt + 1) & 3;
    }
}

// Fused projection GEMM: grid.z selects (X, W, bias, out, scale).
__global__ __launch_bounds__(256) void gemm_proj_kernel(
    const __half* __restrict__ xq, const __half* __restrict__ xk,
    const __half* __restrict__ xv,
    const __half* __restrict__ wq, const __half* __restrict__ wk,
    const __half* __restrict__ wv,
    const float* __restrict__ bq, const float* __restrict__ bk,
    const float* __restrict__ bv,
    __half* __restrict__ oq, __half* __restrict__ ok, __half* __restrict__ ov)
{
    const uint32_t sb = smem_u32(dynsmem);
    const int tid = threadIdx.x, wid = tid >> 5, lane = tid & 31;
    const int wm = wid >> 2, wn = wid & 3;
    const int n0 = blockIdx.x * BN, m0 = blockIdx.y * BM;
    const int z = blockIdx.z;

    const __half* Ab  = z == 0 ? xq : (z == 1 ? xk : xv);
    const __half* Wb  = z == 0 ? wq : (z == 1 ? wk : wv);
    const float* bias = z == 0 ? bq : (z == 1 ? bk : bv);
    __half* outp      = z == 0 ? oq : (z == 1 ? ok : ov);
    const float oscale = z == 0 ? SCALE_L2E : 1.0f;

    float acc[4][4][4];
    gemm_mainloop(sb, Ab + (size_t)m0 * D_, Wb + (size_t)n0 * D_,
                  tid, lane, wm, wn, acc);

    const int g = lane >> 2, tq = lane & 3;
#pragma unroll
    for (int mt = 0; mt < 4; mt++) {
#pragma unroll
        for (int nt = 0; nt < 4; nt++) {
            int row = m0 + wm * 64 + mt * 16 + g;
            int col = n0 + wn * 32 + nt * 8 + tq * 2;
            float2 bv2 = *(const float2*)&bias[col];
            float v0 = (acc[mt][nt][0] + bv2.x) * oscale;
            float v1 = (acc[mt][nt][1] + bv2.y) * oscale;
            float v2 = (acc[mt][nt][2] + bv2.x) * oscale;
            float v3 = (acc[mt][nt][3] + bv2.y) * oscale;
            int bb = row >> 11, s = row & 2047, hh = col >> 6, d = col & 63;
            size_t i0 = ((size_t)(bb * H_ + hh) * S_ + s) * HD_ + d;
            size_t i1 = i0 + 8 * HD_;
            *(uint32_t*)&outp[i0] = pack2h(v0, v1);
            *(uint32_t*)&outp[i1] = pack2h(v2, v3);
        }
    }
}

// Final GEMM: single-A fp16, fp32 out.
__global__ __launch_bounds__(256) void gemm_out_kernel(
    const __half* __restrict__ Ahi, const __half* __restrict__ Bw,
    const float* __restrict__ bias, float* __restrict__ out)
{
    const uint32_t sb = smem_u32(dynsmem);
    const int tid = threadIdx.x, wid = tid >> 5, lane = tid & 31;
    const int wm = wid >> 2, wn = wid & 3;
    const int n0 = blockIdx.x * BN, m0 = blockIdx.y * BM;

    float acc[4][4][4];
    gemm_mainloop(sb, Ahi + (size_t)m0 * D_, Bw + (size_t)n0 * D_,
                  tid, lane, wm, wn, acc);

    const int g = lane >> 2, tq = lane & 3;
#pragma unroll
    for (int mt = 0; mt < 4; mt++) {
#pragma unroll
        for (int nt = 0; nt < 4; nt++) {
            int row = m0 + wm * 64 + mt * 16 + g;
            int col = n0 + wn * 32 + nt * 8 + tq * 2;
            float2 bv2 = *(const float2*)&bias[col];
            *(float2*)&out[(size_t)row * D_ + col] =
                make_float2(acc[mt][nt][0] + bv2.x, acc[mt][nt][1] + bv2.y);
            *(float2*)&out[(size_t)(row + 8) * D_ + col] =
                make_float2(acc[mt][nt][2] + bv2.x, acc[mt][nt][3] + bv2.y);
        }
    }
}

// ---------------- gather: compact K rows; compact + transpose V --------------
__global__ __launch_bounds__(256) void gather_kv_kernel()
{
    __shared__ __align__(16) unsigned short ts[64 * 66];
    __shared__ int sidx[64];
    const int b = blockIdx.z, h = blockIdx.y, st = blockIdx.x;
    const int bh = b * H_ + h;
    const int j0 = st * 64;
    const int tid = threadIdx.x;
    const int cnt = g_cnt[b];

    if (tid < 64) sidx[tid] = (j0 + tid < cnt) ? g_idx[b][j0 + tid] : -1;
    __syncthreads();

    {
        int r = tid >> 2, part = tid & 3;
        int s = sidx[r];
        const uint4* srcp = (const uint4*)(g_k + ((size_t)bh * S_ + (s < 0 ? 0 : s)) * HD_)
                            + part * 2;
        uint4 z = make_uint4(0, 0, 0, 0);
        uint4 v0 = s >= 0 ? srcp[0] : z;
        uint4 v1 = s >= 0 ? srcp[1] : z;
        uint4* dstp = (uint4*)(g_kc + ((size_t)bh * S_ + j0 + r) * HD_) + part * 2;
        dstp[0] = v0;
        dstp[1] = v1;
    }

#pragma unroll
    for (int i = 0; i < 8; i++) {
        int flat = tid + i * 256;
        int r = flat >> 5, c2 = flat & 31;
        int s = sidx[r];
        uint32_t v = 0;
        if (s >= 0)
            v = ((const uint32_t*)(g_v + ((size_t)bh * S_ + s) * HD_))[c2];
        *(uint32_t*)&ts[r * 66 + c2 * 2] = v;
    }
    __syncthreads();
    uint32_t* dst = (uint32_t*)(g_vt + (size_t)bh * HD_ * S_ + j0);
#pragma unroll
    for (int i = 0; i < 8; i++) {
        int flat = tid + i * 256;
        int d = flat >> 5, sp = flat & 31;
        uint32_t v = (uint32_t)ts[(2 * sp) * 66 + d] |
                     ((uint32_t)ts[(2 * sp + 1) * 66 + d] << 16);
        dst[(size_t)d * (S_ / 2) + sp] = v;
    }
}

// ---------------- tensor-core flash attention, 3-stage KV pipeline -----------
#define FQ   0u
#define FKV  18432u
#define FBUF 18432u
#define FLASH_SMEM 73728   // Q + 3 KV stages

__global__ __launch_bounds__(256) void flash_tc_kernel()
{
    char* sm = dynsmem;
    const uint32_t sb = smem_u32(sm);
    const int tid = threadIdx.x, w = tid >> 5, lane = tid & 31;
    const int lr = lane & 7, lq = lane >> 3, g = lane >> 2, q = lane & 3;
    const int b = blockIdx.z, h = blockIdx.y;
    const int bh = b * H_ + h;
    const int q0 = blockIdx.x * 128;

    const int cnt = g_cnt[b];
    int nkt = (cnt + 63) >> 6;
    if (nkt < 1) nkt = 1;

    const __half* Qp  = g_q  + ((size_t)bh * S_ + q0) * HD_;
    const __half* Kp  = g_kc + (size_t)bh * S_ * HD_;
    const __half* Vtp = g_vt + (size_t)bh * HD_ * S_;

    {
        int r = tid >> 1, halfr = tid & 1;
        const __half* src = Qp + (size_t)r * HD_ + halfr * 32;
        uint32_t dst = sb + FQ + (uint32_t)r * 144u + (uint32_t)halfr * 64u;
#pragma unroll
        for (int j = 0; j < 4; j++) cp16(dst + j * 16, src + j * 8);
    }
    cp_commit();

    auto load_tile = [&](int kt, int buf) {
        int k0 = kt * 64;
        int which = tid & 1;
        int halfr = (tid >> 1) & 1;
        int r = tid >> 2;
        uint32_t dst = sb + FKV + (uint32_t)buf * FBUF + (uint32_t)which * 9216u +
                       (uint32_t)r * 144u + (uint32_t)halfr * 64u;
        const __half* src = which ? (Vtp + (size_t)r * S_ + k0 + halfr * 32)
                                  : (Kp + (size_t)(k0 + r) * HD_ + halfr * 32);
#pragma unroll
        for (int j = 0; j < 4; j++) cp16(dst + j * 16, src + j * 8);
        cp_commit();
    };
    load_tile(0, 0);
    load_tile(1, 1);

    asm volatile("cp.async.wait_group 2;" ::: "memory");
    __syncthreads();

    uint32_t qf[4][4];
    {
        uint32_t aoff = (uint32_t)(w * 16 + (lq & 1) * 8 + lr) * 144u +
                        (uint32_t)((lq >> 1) * 8) * 2u;
#pragma unroll
        for (int ks = 0; ks < 4; ks++)
            ldsm4(qf[ks], sb + FQ + aoff + ks * 32);
    }

    float o[8][4];
#pragma unroll
    for (int i = 0; i < 8; i++) { o[i][0] = o[i][1] = o[i][2] = o[i][3] = 0.f; }
    float m0r = -1e30f, m1r = -1e30f, l0 = 0.f, l1 = 0.f;
    const uint32_t boff = (uint32_t)((lq >> 1) * 8 + lr) * 144u +
                          (uint32_t)((lq & 1) * 8) * 2u;

    int cur = 0, nxt = 2;
#pragma unroll 1
    for (int kt = 0; kt < nkt; kt++) {
        if (kt >= nkt - 2) asm volatile("cp.async.wait_group 0;" ::: "memory");
        else               asm volatile("cp.async.wait_group 1;" ::: "memory");
        __syncthreads();

        const uint32_t kb = sb + FKV + (uint32_t)cur * FBUF;

        float sc[8][4];
#pragma unroll
        for (int i = 0; i < 8; i++) { sc[i][0] = sc[i][1] = sc[i][2] = sc[i][3] = 0.f; }

#pragma unroll
        for (int ks = 0; ks < 4; ks++) {
            uint32_t kf[4][4];
#pragma unroll
            for (int np = 0; np < 4; np++)
                ldsm4(kf[np], kb + boff + (uint32_t)np * 2304u + ks * 32);
#pragma unroll
            for (int nt = 0; nt < 8; nt++)
                mma_f16(sc[nt], qf[ks], &kf[nt >> 1][(nt & 1) * 2]);
        }

        if (kt + 2 < nkt) load_tile(kt + 2, nxt);

        // pads exist only in the LAST tile: mask only there (bit-identical)
        if (kt == nkt - 1) {
#pragma unroll
            for (int nt = 0; nt < 8; nt++) {
                int j = kt * 64 + nt * 8 + q * 2;
                bool p0 = j < cnt, p1 = j + 1 < cnt;
                sc[nt][0] = p0 ? sc[nt][0] : -1e10f;
                sc[nt][1] = p1 ? sc[nt][1] : -1e10f;
                sc[nt][2] = p0 ? sc[nt][2] : -1e10f;
                sc[nt][3] = p1 ? sc[nt][3] : -1e10f;
            }
        }

        float tm0 = -1e30f, tm1 = -1e30f;
#pragma unroll
        for (int nt = 0; nt < 8; nt++) {
            tm0 = fmaxf(tm0, fmaxf(sc[nt][0], sc[nt][1]));
            tm1 = fmaxf(tm1, fmaxf(sc[nt][2], sc[nt][3]));
        }
        tm0 = fmaxf(tm0, __shfl_xor_sync(0xffffffffu, tm0, 1));
        tm0 = fmaxf(tm0, __shfl_xor_sync(0xffffffffu, tm0, 2));
        tm1 = fmaxf(tm1, __shfl_xor_sync(0xffffffffu, tm1, 1));
        tm1 = fmaxf(tm1, __shfl_xor_sync(0xffffffffu, tm1, 2));
        float nm0 = fmaxf(m0r, tm0), nm1 = fmaxf(m1r, tm1);
        float al0 = exp2f(m0r - nm0), al1 = exp2f(m1r - nm1);
        m0r = nm0; m1r = nm1;
        float rs0 = 0.f, rs1 = 0.f;
#pragma unroll
        for (int nt = 0; nt < 8; nt++) {
            sc[nt][0] = exp2f(sc[nt][0] - nm0);
            sc[nt][1] = exp2f(sc[nt][1] - nm0);
            sc[nt][2] = exp2f(sc[nt][2] - nm1);
            sc[nt][3] = exp2f(sc[nt][3] - nm1);
            rs0 += sc[nt][0] + sc[nt][1];
            rs1 += sc[nt][2] + sc[nt][3];
        }
        rs0 += __shfl_xor_sync(0xffffffffu, rs0, 1);
        rs0 += __shfl_xor_sync(0xffffffffu, rs0, 2);
        rs1 += __shfl_xor_sync(0xffffffffu, rs1, 1);
        rs1 += __shfl_xor_sync(0xffffffffu, rs1, 2);
        l0 = l0 * al0 + rs0;
        l1 = l1 * al1 + rs1;
        // rescale only when the running max actually changed (x1.0 is identity)
        if (!(al0 == 1.f && al1 == 1.f)) {
#pragma unroll
            for (int nt = 0; nt < 8; nt++) {
                o[nt][0] *= al0; o[nt][1] *= al0; o[nt][2] *= al1; o[nt][3] *= al1;
            }
        }

#pragma unroll
        for (int ks = 0; ks < 4; ks++) {
            const int t0 = 2 * ks, t1 = t0 + 1;
            uint32_t ah[4];
            ah[0] = pack2h(sc[t0][0], sc[t0][1]);
            ah[1] = pack2h(sc[t0][2], sc[t0][3]);
            ah[2] = pack2h(sc[t1][0], sc[t1][1]);
            ah[3] = pack2h(sc[t1][2], sc[t1][3]);
            uint32_t vf[4][4];
#pragma unroll
            for (int np = 0; np < 4; np++)
                ldsm4(vf[np], kb + 9216u + boff + (uint32_t)np * 2304u + ks * 32);
#pragma unroll
            for (int nt = 0; nt < 8; nt++)
                mma_f16(o[nt], ah, &vf[nt >> 1][(nt & 1) * 2]);
        }
        cur = cur == 2 ? 0 : cur + 1;
        nxt = nxt == 2 ? 0 : nxt + 1;
    }

    float inv0 = 1.f / l0, inv1 = 1.f / l1;
    size_t row0 = (size_t)(b * S_ + q0 + w * 16 + g);
    int colb = h * HD_;
#pragma unroll
    for (int nt = 0; nt < 8; nt++) {
        int col = colb + nt * 8 + q * 2;
        *(uint32_t*)&g_hh[row0 * D_ + col] = pack2h(o[nt][0] * inv0, o[nt][1] * inv0);
        *(uint32_t*)&g_hh[(row0 + 8) * D_ + col] = pack2h(o[nt][2] * inv1, o[nt][3] * inv1);
    }
}

// ---------------------------------------------------------------------------
extern "C" void kernel_launch(void* const* d_in, const int* in_sizes, int n_in,
                              void* d_out, int out_size)
{
    const float* query = (const float*)d_in[0];
    const float* key   = (const float*)d_in[1];
    const float* value = (const float*)d_in[2];
    const int*   mask  = (const int*)d_in[3];
    const float* Wq = (const float*)d_in[4];
    const float* bq = (const float*)d_in[5];
    const float* Wk = (const float*)d_in[6];
    const float* bk = (const float*)d_in[7];
    const float* Wv = (const float*)d_in[8];
    const float* bv = (const float*)d_in[9];
    const float* Wo = (const float*)d_in[10];
    const float* bo = (const float*)d_in[11];
    float* out = (float*)d_out;

    __half *xq,*xk,*xv,*wq,*wk,*wv,*wo,*hh,*qq,*kk,*vv;
    cudaGetSymbolAddress((void**)&xq, g_xq);
    cudaGetSymbolAddress((void**)&xk, g_xk);
    cudaGetSymbolAddress((void**)&xv, g_xv);
    cudaGetSymbolAddress((void**)&wq, g_wq);
    cudaGetSymbolAddress((void**)&wk, g_wk);
    cudaGetSymbolAddress((void**)&wv, g_wv);
    cudaGetSymbolAddress((void**)&wo, g_wo);
    cudaGetSymbolAddress((void**)&qq, g_q);
    cudaGetSymbolAddress((void**)&kk, g_k);
    cudaGetSymbolAddress((void**)&vv, g_v);
    cudaGetSymbolAddress((void**)&hh, g_hh);

    static int attr_set = 0;
    if (!attr_set) {
        cudaFuncSetAttribute((const void*)gemm_proj_kernel,
                             cudaFuncAttributeMaxDynamicSharedMemorySize, GEMM_SMEM);
        cudaFuncSetAttribute((const void*)gemm_out_kernel,
                             cudaFuncAttributeMaxDynamicSharedMemorySize, GEMM_SMEM);
        cudaFuncSetAttribute((const void*)flash_tc_kernel,
                             cudaFuncAttributeMaxDynamicSharedMemorySize, FLASH_SMEM);
        attr_set = 1;
    }

    const int NX4 = M_ * D_ / 4;
    cvt_all_kernel<<<dim3((NX4 + 255) / 256, 7), 256>>>(
        query, key, value, Wq, Wk, Wv, Wo, xq, xk, xv, wq, wk, wv, wo);

    mask_compact_kernel<<<B_, 256>>>(mask);

    gemm_proj_kernel<<<dim3(D_ / BN, M_ / BM, 3), 256, GEMM_SMEM>>>(
        xq, xk, xv, wq, wk, wv, bq, bk, bv, qq, kk, vv);

    gather_kv_kernel<<<dim3(S_ / 64, H_, B_), 256>>>();

    flash_tc_kernel<<<dim3(S_ / 128, H_, B_), 256, FLASH_SMEM>>>();

    gemm_out_kernel<<<dim3(D_ / BN, M_ / BM), 256, GEMM_SMEM>>>(hh, wo, bo, out);
}